// round 1
// baseline (speedup 1.0000x reference)
#include <cuda_runtime.h>

#define NN 50000
#define CC 8
#define DD 64
#define EE 100000
#define PITCH 68      // padded row for 64-wide matrices (bank-conflict-friendly, 16B aligned)
#define QPITCH 196    // padded row for qkv (192 cols)

// -------- scratch (device globals: allocation-free) --------
__device__ float g_hA[(size_t)NN * 512];
__device__ float g_hB[(size_t)NN * 512];
__device__ float g_inv[NN];
__device__ int   g_any;

// ---------------- small utility kernels ----------------

__global__ void init_any_kernel() { g_any = 0; }

// Detect int64 vs int32 edge_index: for int64 (values < 2^31) every odd 32-bit
// word of the first row is zero. Scan only first 2*EE ints (in-bounds for both).
__global__ void detect_kernel(const int* __restrict__ ei) {
    int i = blockIdx.x * blockDim.x + threadIdx.x;
    int v = 0;
    for (int k = i; k < EE; k += gridDim.x * blockDim.x) v |= ei[2 * k + 1];
    if (v) atomicOr(&g_any, 1);
}

__global__ void embed_kernel(const float* __restrict__ x,
                             const float* __restrict__ nw,
                             const float* __restrict__ nb) {
    int i = blockIdx.x * blockDim.x + threadIdx.x;
    if (i < NN * 512) {
        int n = i >> 9;
        int r = i & 511;
        g_hA[i] = x[n * 8 + (r >> 6)] * nw[r] + nb[r];
    }
}

__global__ void zero_cnt_kernel() {
    int i = blockIdx.x * blockDim.x + threadIdx.x;
    if (i < NN) g_inv[i] = 0.f;
}

__global__ void count_kernel(const int* __restrict__ ei) {
    int e = blockIdx.x * blockDim.x + threadIdx.x;
    if (e < EE) {
        int is64 = (g_any == 0);
        int t = is64 ? ei[2 * (EE + e)] : ei[EE + e];
        atomicAdd(&g_inv[t], 1.0f);
    }
}

__global__ void fin_cnt_kernel() {
    int i = blockIdx.x * blockDim.x + threadIdx.x;
    if (i < NN) g_inv[i] = 1.0f / fmaxf(g_inv[i], 1.0f);
}

__global__ void zero_h_kernel(int which) {
    float4* p = (float4*)(which ? g_hB : g_hA);
    size_t i = (size_t)blockIdx.x * blockDim.x + threadIdx.x;
    if (i < (size_t)NN * 128) p[i] = make_float4(0.f, 0.f, 0.f, 0.f);
}

// ---------------- main per-edge transformer kernel ----------------
// Persistent CTAs: weights for one layer staged into SMEM once, then each CTA
// loops over edges; 4 edges concurrently (sub-blocks of 128 threads).

__global__ void __launch_bounds__(512, 1)
edge_kernel(const int* __restrict__ ei, int dir,
            const float* __restrict__ bpw, const float* __restrict__ bpb,
            const float* __restrict__ ipw, const float* __restrict__ ipb,
            const float* __restrict__ opw, const float* __restrict__ opb,
            const float* __restrict__ ln1g, const float* __restrict__ ln1b,
            const float* __restrict__ ln2g, const float* __restrict__ ln2b,
            const float* __restrict__ w1,  const float* __restrict__ fb1,
            const float* __restrict__ w2,  const float* __restrict__ fb2) {
    extern __shared__ float sm[];
    float* s_ipw = sm;                          // 192*68
    float* s_opw = s_ipw + 192 * PITCH;         // 64*68
    float* s_w1  = s_opw + 64 * PITCH;
    float* s_w2  = s_w1  + 64 * PITCH;
    float* s_bw  = s_w2  + 64 * PITCH;
    float* s_b   = s_bw  + 64 * PITCH;          // 704 floats of biases/ln params
    float* s_act = s_b + 704;

    const float* hin  = dir ? g_hB : g_hA;
    float*       hout = dir ? g_hA : g_hB;

    const int tid = threadIdx.x;

    // ---- stage weights (once per CTA) ----
    for (int i = tid; i < 192 * 64; i += 512)
        s_ipw[(i >> 6) * PITCH + (i & 63)] = ipw[i];
    for (int i = tid; i < 64 * 64; i += 512) {
        int r = (i >> 6) * PITCH + (i & 63);
        s_opw[r] = opw[i]; s_w1[r] = w1[i]; s_w2[r] = w2[i]; s_bw[r] = bpw[i];
    }
    for (int i = tid; i < 192; i += 512) s_b[i] = ipb[i];
    if (tid < 64) {
        s_b[192 + tid] = opb[tid];  s_b[256 + tid] = fb1[tid];
        s_b[320 + tid] = fb2[tid];  s_b[384 + tid] = ln1g[tid];
        s_b[448 + tid] = ln1b[tid]; s_b[512 + tid] = ln2g[tid];
        s_b[576 + tid] = ln2b[tid]; s_b[640 + tid] = bpb[tid];
    }
    __syncthreads();

    const int sub = tid >> 7;      // 0..3 : which edge slot
    const int st  = tid & 127;     // thread within sub-block
    float* xs  = s_act + sub * 5888;       // 8*68   source tokens (bproj input)
    float* xc  = xs + 8 * PITCH;           // 16*68  sequence buffer
    float* qv  = xc + 16 * PITCH;          // 16*196 qkv / tmp
    float* ao  = qv + 16 * QPITCH;         // 16*68  attn out / ff hidden
    float* stt = ao + 16 * PITCH;          // 32     LN stats

    const int is64 = (g_any == 0);

    for (int base = blockIdx.x * 4; base < EE; base += gridDim.x * 4) {
        int e = base + sub;
        bool valid = e < EE;
        int tgt = 0; float ic = 0.f;

        // ---- P0: gather h[tgt] -> xc[0..7], h[src] -> xs ----
        if (valid) {
            int src = is64 ? ei[2 * e]        : ei[e];
            tgt     = is64 ? ei[2 * (EE + e)] : ei[EE + e];
            ic = g_inv[tgt];
            int r = st >> 4, d = (st & 15) << 2;
            float4 vi = *(const float4*)(hin + (size_t)tgt * 512 + r * 64 + d);
            float4 vj = *(const float4*)(hin + (size_t)src * 512 + r * 64 + d);
            *(float4*)(xc + r * PITCH + d) = vi;
            *(float4*)(xs + r * PITCH + d) = vj;
        }
        __syncthreads();

        // ---- P1: bproj  xc[8+c][j] = xs[c] . bpw[j] + bpb[j] ----
        if (valid) {
            int r = st & 7, g = st >> 3;
            float4 xr[16];
            #pragma unroll
            for (int i = 0; i < 16; i++) xr[i] = *(const float4*)(xs + r * PITCH + i * 4);
            #pragma unroll 2
            for (int k = 0; k < 4; k++) {
                int j = g + (k << 4);
                const float4* wr = (const float4*)(s_bw + j * PITCH);
                float a0 = s_b[640 + j], a1 = 0.f, a2 = 0.f, a3 = 0.f;
                #pragma unroll
                for (int i = 0; i < 16; i++) {
                    float4 w4 = wr[i];
                    a0 = fmaf(xr[i].x, w4.x, a0); a1 = fmaf(xr[i].y, w4.y, a1);
                    a2 = fmaf(xr[i].z, w4.z, a2); a3 = fmaf(xr[i].w, w4.w, a3);
                }
                xc[(8 + r) * PITCH + j] = (a0 + a1) + (a2 + a3);
            }
        }
        __syncthreads();

        // ---- P2: qkv = xc @ ipw^T + ipb  (16 x 192) ----
        if (valid) {
            int r = st & 15, g = st >> 4;
            float4 xr[16];
            #pragma unroll
            for (int i = 0; i < 16; i++) xr[i] = *(const float4*)(xc + r * PITCH + i * 4);
            #pragma unroll 2
            for (int k = 0; k < 24; k++) {
                int j = g + (k << 3);
                const float4* wr = (const float4*)(s_ipw + j * PITCH);
                float a0 = s_b[j], a1 = 0.f, a2 = 0.f, a3 = 0.f;
                #pragma unroll
                for (int i = 0; i < 16; i++) {
                    float4 w4 = wr[i];
                    a0 = fmaf(xr[i].x, w4.x, a0); a1 = fmaf(xr[i].y, w4.y, a1);
                    a2 = fmaf(xr[i].z, w4.z, a2); a3 = fmaf(xr[i].w, w4.w, a3);
                }
                qv[r * QPITCH + j] = (a0 + a1) + (a2 + a3);
            }
        }
        __syncthreads();

        // ---- P3: attention (threads 0..63: one (head,query) each) ----
        if (valid && st < 64) {
            int hh = st >> 4, q = st & 15;
            float4 qr[4];
            const float4* qrow = (const float4*)(qv + q * QPITCH + hh * 16);
            #pragma unroll
            for (int i = 0; i < 4; i++) qr[i] = qrow[i];
            float sc[16], m = -1e30f;
            #pragma unroll
            for (int k = 0; k < 16; k++) {
                const float4* kr = (const float4*)(qv + k * QPITCH + 64 + hh * 16);
                float a0 = 0.f, a1 = 0.f, a2 = 0.f, a3 = 0.f;
                #pragma unroll
                for (int i = 0; i < 4; i++) {
                    float4 k4 = kr[i];
                    a0 = fmaf(qr[i].x, k4.x, a0); a1 = fmaf(qr[i].y, k4.y, a1);
                    a2 = fmaf(qr[i].z, k4.z, a2); a3 = fmaf(qr[i].w, k4.w, a3);
                }
                float a = ((a0 + a1) + (a2 + a3)) * 0.25f;
                sc[k] = a; m = fmaxf(m, a);
            }
            float ssum = 0.f;
            #pragma unroll
            for (int k = 0; k < 16; k++) { sc[k] = __expf(sc[k] - m); ssum += sc[k]; }
            float rs = 1.f / ssum;
            float4 o0 = make_float4(0.f,0.f,0.f,0.f), o1 = o0, o2 = o0, o3 = o0;
            #pragma unroll
            for (int k = 0; k < 16; k++) {
                float a = sc[k];
                const float4* vr = (const float4*)(qv + k * QPITCH + 128 + hh * 16);
                float4 v0 = vr[0], v1 = vr[1], v2 = vr[2], v3 = vr[3];
                o0.x = fmaf(a, v0.x, o0.x); o0.y = fmaf(a, v0.y, o0.y);
                o0.z = fmaf(a, v0.z, o0.z); o0.w = fmaf(a, v0.w, o0.w);
                o1.x = fmaf(a, v1.x, o1.x); o1.y = fmaf(a, v1.y, o1.y);
                o1.z = fmaf(a, v1.z, o1.z); o1.w = fmaf(a, v1.w, o1.w);
                o2.x = fmaf(a, v2.x, o2.x); o2.y = fmaf(a, v2.y, o2.y);
                o2.z = fmaf(a, v2.z, o2.z); o2.w = fmaf(a, v2.w, o2.w);
                o3.x = fmaf(a, v3.x, o3.x); o3.y = fmaf(a, v3.y, o3.y);
                o3.z = fmaf(a, v3.z, o3.z); o3.w = fmaf(a, v3.w, o3.w);
            }
            float4* dst = (float4*)(ao + q * PITCH + hh * 16);
            dst[0] = make_float4(o0.x*rs, o0.y*rs, o0.z*rs, o0.w*rs);
            dst[1] = make_float4(o1.x*rs, o1.y*rs, o1.z*rs, o1.w*rs);
            dst[2] = make_float4(o2.x*rs, o2.y*rs, o2.z*rs, o2.w*rs);
            dst[3] = make_float4(o3.x*rs, o3.y*rs, o3.z*rs, o3.w*rs);
        }
        __syncthreads();

        // ---- P4: out_proj + residual -> qv[.][0..63] (tmp) ----
        if (valid) {
            int r = st & 15, g = st >> 4;
            float4 xr[16];
            #pragma unroll
            for (int i = 0; i < 16; i++) xr[i] = *(const float4*)(ao + r * PITCH + i * 4);
            #pragma unroll 2
            for (int k = 0; k < 8; k++) {
                int j = g + (k << 3);
                const float4* wr = (const float4*)(s_opw + j * PITCH);
                float a0 = s_b[192 + j], a1 = 0.f, a2 = 0.f, a3 = 0.f;
                #pragma unroll
                for (int i = 0; i < 16; i++) {
                    float4 w4 = wr[i];
                    a0 = fmaf(xr[i].x, w4.x, a0); a1 = fmaf(xr[i].y, w4.y, a1);
                    a2 = fmaf(xr[i].z, w4.z, a2); a3 = fmaf(xr[i].w, w4.w, a3);
                }
                qv[r * QPITCH + j] = (a0 + a1) + (a2 + a3) + xc[r * PITCH + j];
            }
        }
        __syncthreads();

        // ---- P5: LayerNorm1 -> xc ----
        if (valid && st < 16) {
            const float4* row = (const float4*)(qv + st * QPITCH);
            float mu = 0.f;
            #pragma unroll
            for (int i = 0; i < 16; i++) { float4 r4 = row[i]; mu += (r4.x + r4.y) + (r4.z + r4.w); }
            mu *= 0.015625f;
            float v = 0.f;
            #pragma unroll
            for (int i = 0; i < 16; i++) {
                float4 r4 = row[i];
                float t0 = r4.x - mu, t1 = r4.y - mu, t2 = r4.z - mu, t3 = r4.w - mu;
                v = fmaf(t0, t0, v); v = fmaf(t1, t1, v);
                v = fmaf(t2, t2, v); v = fmaf(t3, t3, v);
            }
            stt[st] = mu;
            stt[16 + st] = rsqrtf(v * 0.015625f + 1e-5f);
        }
        __syncthreads();
        if (valid) {
            #pragma unroll
            for (int i = 0; i < 8; i++) {
                int idx = st * 8 + i;
                int s = idx >> 6, d = idx & 63;
                xc[s * PITCH + d] =
                    (qv[s * QPITCH + d] - stt[s]) * stt[16 + s] * s_b[384 + d] + s_b[448 + d];
            }
        }
        __syncthreads();

        // ---- P6: FF1 + relu -> ao ----
        if (valid) {
            int r = st & 15, g = st >> 4;
            float4 xr[16];
            #pragma unroll
            for (int i = 0; i < 16; i++) xr[i] = *(const float4*)(xc + r * PITCH + i * 4);
            #pragma unroll 2
            for (int k = 0; k < 8; k++) {
                int f = g + (k << 3);
                const float4* wr = (const float4*)(s_w1 + f * PITCH);
                float a0 = s_b[256 + f], a1 = 0.f, a2 = 0.f, a3 = 0.f;
                #pragma unroll
                for (int i = 0; i < 16; i++) {
                    float4 w4 = wr[i];
                    a0 = fmaf(xr[i].x, w4.x, a0); a1 = fmaf(xr[i].y, w4.y, a1);
                    a2 = fmaf(xr[i].z, w4.z, a2); a3 = fmaf(xr[i].w, w4.w, a3);
                }
                ao[r * PITCH + f] = fmaxf((a0 + a1) + (a2 + a3), 0.f);
            }
        }
        __syncthreads();

        // ---- P7: FF2 + residual -> qv tmp ----
        if (valid) {
            int r = st & 15, g = st >> 4;
            float4 xr[16];
            #pragma unroll
            for (int i = 0; i < 16; i++) xr[i] = *(const float4*)(ao + r * PITCH + i * 4);
            #pragma unroll 2
            for (int k = 0; k < 8; k++) {
                int j = g + (k << 3);
                const float4* wr = (const float4*)(s_w2 + j * PITCH);
                float a0 = s_b[320 + j], a1 = 0.f, a2 = 0.f, a3 = 0.f;
                #pragma unroll
                for (int i = 0; i < 16; i++) {
                    float4 w4 = wr[i];
                    a0 = fmaf(xr[i].x, w4.x, a0); a1 = fmaf(xr[i].y, w4.y, a1);
                    a2 = fmaf(xr[i].z, w4.z, a2); a3 = fmaf(xr[i].w, w4.w, a3);
                }
                qv[r * QPITCH + j] = (a0 + a1) + (a2 + a3) + xc[r * PITCH + j];
            }
        }
        __syncthreads();

        // ---- P8: LayerNorm2 on tokens 0..7 + scaled atomic scatter ----
        if (valid && st < 8) {
            const float4* row = (const float4*)(qv + st * QPITCH);
            float mu = 0.f;
            #pragma unroll
            for (int i = 0; i < 16; i++) { float4 r4 = row[i]; mu += (r4.x + r4.y) + (r4.z + r4.w); }
            mu *= 0.015625f;
            float v = 0.f;
            #pragma unroll
            for (int i = 0; i < 16; i++) {
                float4 r4 = row[i];
                float t0 = r4.x - mu, t1 = r4.y - mu, t2 = r4.z - mu, t3 = r4.w - mu;
                v = fmaf(t0, t0, v); v = fmaf(t1, t1, v);
                v = fmaf(t2, t2, v); v = fmaf(t3, t3, v);
            }
            stt[st] = mu;
            stt[16 + st] = rsqrtf(v * 0.015625f + 1e-5f);
        }
        __syncthreads();
        if (valid) {
            int r = st >> 4, dbase = (st & 15) << 2;
            float mu = stt[r], rstd = stt[16 + r];
            float* dst = hout + (size_t)tgt * 512 + r * 64 + dbase;
            #pragma unroll
            for (int t = 0; t < 4; t++) {
                int d = dbase + t;
                float val = (qv[r * QPITCH + d] - mu) * rstd * s_b[512 + d] + s_b[576 + d];
                atomicAdd(dst + t, val * ic);
            }
        }
        __syncthreads();
    }
}

// ---------------- output head ----------------
__global__ void out_kernel(const float* __restrict__ ow,
                           const float* __restrict__ ob,
                           float* __restrict__ out) {
    __shared__ float shs[8][64];
    int w = threadIdx.x >> 5, lane = threadIdx.x & 31;
    int n = blockIdx.x * 8 + w;
    if (n >= NN) return;
    const float* hr = g_hA + (size_t)n * 512;
    float lo = 0.f, hi = 0.f;
    #pragma unroll
    for (int c = 0; c < 8; c++) { lo += hr[c * 64 + lane]; hi += hr[c * 64 + 32 + lane]; }
    shs[w][lane] = lo; shs[w][lane + 32] = hi;
    __syncwarp();
    float z = -1e30f;
    if (lane < 16) {
        float acc = 8.f * ob[lane];
        const float* wr = ow + lane * 64;
        #pragma unroll
        for (int d = 0; d < 64; d++) acc = fmaf(shs[w][d], wr[d], acc);
        z = acc;
    }
    float m = z;
    #pragma unroll
    for (int off = 8; off; off >>= 1) m = fmaxf(m, __shfl_xor_sync(0xffffffffu, m, off, 16));
    float p = __expf(z - m);
    float s = p;
    #pragma unroll
    for (int off = 8; off; off >>= 1) s += __shfl_xor_sync(0xffffffffu, s, off, 16);
    if (lane < 16) out[n * 16 + lane] = p / s;
}

// ---------------- launch ----------------
extern "C" void kernel_launch(void* const* d_in, const int* in_sizes, int n_in,
                              void* d_out, int out_size) {
    const float* x    = (const float*)d_in[0];
    const int*   ei   = (const int*)d_in[1];
    const float* numw = (const float*)d_in[2];
    const float* numb = (const float*)d_in[3];
    const float* bpw  = (const float*)d_in[4];
    const float* bpb  = (const float*)d_in[5];
    const float* ipw  = (const float*)d_in[6];
    const float* ipb  = (const float*)d_in[7];
    const float* opw  = (const float*)d_in[8];
    const float* opb  = (const float*)d_in[9];
    const float* g1   = (const float*)d_in[10];
    const float* b1   = (const float*)d_in[11];
    const float* g2   = (const float*)d_in[12];
    const float* b2   = (const float*)d_in[13];
    const float* w1   = (const float*)d_in[14];
    const float* fb1  = (const float*)d_in[15];
    const float* w2   = (const float*)d_in[16];
    const float* fb2  = (const float*)d_in[17];
    const float* ow   = (const float*)d_in[18];
    const float* ob   = (const float*)d_in[19];
    float* out = (float*)d_out;

    const int SMEM_BYTES = (192 * PITCH + 4 * 64 * PITCH + 704 + 4 * 5888) * 4;
    cudaFuncSetAttribute(edge_kernel, cudaFuncAttributeMaxDynamicSharedMemorySize, SMEM_BYTES);

    int dev = 0, sms = 148;
    cudaGetDevice(&dev);
    cudaDeviceGetAttribute(&sms, cudaDevAttrMultiProcessorCount, dev);

    init_any_kernel<<<1, 1>>>();
    detect_kernel<<<256, 256>>>(ei);
    embed_kernel<<<(NN * 512 + 255) / 256, 256>>>(x, numw, numb);
    zero_cnt_kernel<<<(NN + 255) / 256, 256>>>();
    count_kernel<<<(EE + 255) / 256, 256>>>(ei);
    fin_cnt_kernel<<<(NN + 255) / 256, 256>>>();

    // layer 0: A -> B
    zero_h_kernel<<<(NN * 128 + 255) / 256, 256>>>(1);
    edge_kernel<<<sms, 512, SMEM_BYTES>>>(ei, 0,
        bpw, bpb, ipw, ipb, opw, opb, g1, b1, g2, b2, w1, fb1, w2, fb2);

    // layer 1: B -> A
    zero_h_kernel<<<(NN * 128 + 255) / 256, 256>>>(0);
    edge_kernel<<<sms, 512, SMEM_BYTES>>>(ei, 1,
        bpw + 64 * 64, bpb + 64, ipw + 192 * 64, ipb + 192, opw + 64 * 64, opb + 64,
        g1 + 64, b1 + 64, g2 + 64, b2 + 64,
        w1 + 64 * 64, fb1 + 64, w2 + 64 * 64, fb2 + 64);

    out_kernel<<<(NN + 7) / 8, 256>>>(ow, ob, out);
}

// round 2
// speedup vs baseline: 2.1169x; 2.1169x over previous
#include <cuda_runtime.h>

#define NN 50000
#define CC 8
#define DD 64
#define EE 100000
#define PITCH 68      // padded row for 64-wide matrices
#define QPITCH 196    // padded row for qkv (192 cols)

// -------- scratch (device globals: allocation-free) --------
__device__ float g_hA[(size_t)NN * 512];
__device__ float g_hB[(size_t)NN * 512];
__device__ float g_inv[NN];
__device__ int   g_any;

// ---------------- small utility kernels ----------------

__global__ void init_any_kernel() { g_any = 0; }

__global__ void detect_kernel(const int* __restrict__ ei) {
    int i = blockIdx.x * blockDim.x + threadIdx.x;
    int v = 0;
    for (int k = i; k < EE; k += gridDim.x * blockDim.x) v |= ei[2 * k + 1];
    if (v) atomicOr(&g_any, 1);
}

__global__ void embed_kernel(const float* __restrict__ x,
                             const float* __restrict__ nw,
                             const float* __restrict__ nb) {
    int i = blockIdx.x * blockDim.x + threadIdx.x;
    if (i < NN * 512) {
        int n = i >> 9;
        int r = i & 511;
        g_hA[i] = x[n * 8 + (r >> 6)] * nw[r] + nb[r];
    }
}

__global__ void zero_cnt_kernel() {
    int i = blockIdx.x * blockDim.x + threadIdx.x;
    if (i < NN) g_inv[i] = 0.f;
}

__global__ void count_kernel(const int* __restrict__ ei) {
    int e = blockIdx.x * blockDim.x + threadIdx.x;
    if (e < EE) {
        int is64 = (g_any == 0);
        int t = is64 ? ei[2 * (EE + e)] : ei[EE + e];
        atomicAdd(&g_inv[t], 1.0f);
    }
}

__global__ void fin_cnt_kernel() {
    int i = blockIdx.x * blockDim.x + threadIdx.x;
    if (i < NN) g_inv[i] = 1.0f / fmaxf(g_inv[i], 1.0f);
}

__global__ void zero_h_kernel(int which) {
    float4* p = (float4*)(which ? g_hB : g_hA);
    size_t i = (size_t)blockIdx.x * blockDim.x + threadIdx.x;
    if (i < (size_t)NN * 128) p[i] = make_float4(0.f, 0.f, 0.f, 0.f);
}

// ---------------- tf32 mma helpers ----------------

__device__ __forceinline__ unsigned f2tf(float x) {
    unsigned r;
    asm("cvt.rna.tf32.f32 %0, %1;" : "=r"(r) : "f"(x));
    return r;
}

__device__ __forceinline__ void mma_tf32(float& c0, float& c1, float& c2, float& c3,
                                         unsigned a0, unsigned a1, unsigned a2, unsigned a3,
                                         unsigned b0, unsigned b1) {
    asm volatile(
        "mma.sync.aligned.m16n8k8.row.col.f32.tf32.tf32.f32 "
        "{%0,%1,%2,%3}, {%4,%5,%6,%7}, {%8,%9}, {%0,%1,%2,%3};\n"
        : "+f"(c0), "+f"(c1), "+f"(c2), "+f"(c3)
        : "r"(a0), "r"(a1), "r"(a2), "r"(a3), "r"(b0), "r"(b1));
}

// load A fragments for a 16x64 tile (8 k-chunks), converting to tf32
__device__ __forceinline__ void load_a(unsigned a[8][4], const float* __restrict__ X,
                                       int xp, int lane) {
    int row = lane >> 2, kc = lane & 3;
    const float* p0 = X + row * xp + kc;
    const float* p1 = X + (row + 8) * xp + kc;
    #pragma unroll
    for (int kb = 0; kb < 8; kb++) {
        a[kb][0] = f2tf(p0[kb * 8]);
        a[kb][1] = f2tf(p1[kb * 8]);
        a[kb][2] = f2tf(p0[kb * 8 + 4]);
        a[kb][3] = f2tf(p1[kb * 8 + 4]);
    }
}

// one 16x8 output tile: C[:, jbase..jbase+8) = A(16x64) @ W^T + bias (+epilogue)
// EPI: 0 = plain, 1 = relu, 2 = add residual R
// ROWS8: write only rows 0..7
template<int EPI, bool ROWS8>
__device__ __forceinline__ void gemm_tile(const unsigned a[8][4],
                                          const float* __restrict__ W,   // tf32-bits in float smem
                                          const float* __restrict__ bias,
                                          int jbase,
                                          float* __restrict__ C, int cp,
                                          const float* __restrict__ R, int rp,
                                          int lane) {
    int g = lane >> 2, tg = lane & 3;
    int col0 = jbase + 2 * tg;
    float c0 = bias[col0], c1 = bias[col0 + 1], c2 = c0, c3 = c1;
    const float* wr = W + (jbase + g) * PITCH;
    #pragma unroll
    for (int kb = 0; kb < 8; kb++) {
        unsigned b0 = __float_as_uint(wr[kb * 8 + tg]);
        unsigned b1 = __float_as_uint(wr[kb * 8 + tg + 4]);
        mma_tf32(c0, c1, c2, c3, a[kb][0], a[kb][1], a[kb][2], a[kb][3], b0, b1);
    }
    if (EPI == 2) {
        c0 += R[g * rp + col0];       c1 += R[g * rp + col0 + 1];
        c2 += R[(g + 8) * rp + col0]; c3 += R[(g + 8) * rp + col0 + 1];
    }
    if (EPI == 1) {
        c0 = fmaxf(c0, 0.f); c1 = fmaxf(c1, 0.f);
        c2 = fmaxf(c2, 0.f); c3 = fmaxf(c3, 0.f);
    }
    *(float2*)(C + g * cp + col0) = make_float2(c0, c1);
    if (!ROWS8) *(float2*)(C + (g + 8) * cp + col0) = make_float2(c2, c3);
}

// ---------------- main per-edge transformer kernel ----------------

__global__ void __launch_bounds__(512, 1)
edge_kernel(const int* __restrict__ ei, int dir,
            const float* __restrict__ bpw, const float* __restrict__ bpb,
            const float* __restrict__ ipw, const float* __restrict__ ipb,
            const float* __restrict__ opw, const float* __restrict__ opb,
            const float* __restrict__ ln1g, const float* __restrict__ ln1b,
            const float* __restrict__ ln2g, const float* __restrict__ ln2b,
            const float* __restrict__ w1,  const float* __restrict__ fb1,
            const float* __restrict__ w2,  const float* __restrict__ fb2) {
    extern __shared__ float sm[];
    float* s_ipw = sm;                          // 192*68
    float* s_opw = s_ipw + 192 * PITCH;         // 64*68
    float* s_w1  = s_opw + 64 * PITCH;
    float* s_w2  = s_w1  + 64 * PITCH;
    float* s_bw  = s_w2  + 64 * PITCH;
    float* s_b   = s_bw  + 64 * PITCH;          // 704 floats biases/ln
    float* s_act = s_b + 704;

    const float* hin  = dir ? g_hB : g_hA;
    float*       hout = dir ? g_hA : g_hB;

    const int tid = threadIdx.x;

    // ---- stage weights once, pre-rounded to tf32 ----
    for (int i = tid; i < 192 * 64; i += 512)
        s_ipw[(i >> 6) * PITCH + (i & 63)] = __uint_as_float(f2tf(ipw[i]));
    for (int i = tid; i < 64 * 64; i += 512) {
        int r = (i >> 6) * PITCH + (i & 63);
        s_opw[r] = __uint_as_float(f2tf(opw[i]));
        s_w1[r]  = __uint_as_float(f2tf(w1[i]));
        s_w2[r]  = __uint_as_float(f2tf(w2[i]));
        s_bw[r]  = __uint_as_float(f2tf(bpw[i]));
    }
    for (int i = tid; i < 192; i += 512) s_b[i] = ipb[i];
    if (tid < 64) {
        s_b[192 + tid] = opb[tid];  s_b[256 + tid] = fb1[tid];
        s_b[320 + tid] = fb2[tid];  s_b[384 + tid] = ln1g[tid];
        s_b[448 + tid] = ln1b[tid]; s_b[512 + tid] = ln2g[tid];
        s_b[576 + tid] = ln2b[tid]; s_b[640 + tid] = bpb[tid];
    }
    __syncthreads();

    const int sub  = tid >> 7;     // 0..3 edge slot
    const int st   = tid & 127;
    const int warp = st >> 5;      // warp within sub-block
    const int lane = st & 31;
    float* xs  = s_act + sub * 5888;       // 8*68
    float* xc  = xs + 8 * PITCH;           // 16*68
    float* qv  = xc + 16 * PITCH;          // 16*196
    float* ao  = qv + 16 * QPITCH;         // 16*68
    float* stt = ao + 16 * PITCH;          // 32

    const int is64 = (g_any == 0);

    for (int base = blockIdx.x * 4; base < EE; base += gridDim.x * 4) {
        int e = base + sub;
        bool valid = e < EE;
        int tgt = 0; float ic = 0.f;

        // ---- P0: gather ----
        if (valid) {
            int src = is64 ? ei[2 * e]        : ei[e];
            tgt     = is64 ? ei[2 * (EE + e)] : ei[EE + e];
            ic = g_inv[tgt];
            int r = st >> 4, d = (st & 15) << 2;
            float4 vi = *(const float4*)(hin + (size_t)tgt * 512 + r * 64 + d);
            float4 vj = *(const float4*)(hin + (size_t)src * 512 + r * 64 + d);
            *(float4*)(xc + r * PITCH + d) = vi;
            *(float4*)(xs + r * PITCH + d) = vj;
        }
        __syncthreads();

        // ---- P1: bproj -> xc rows 8..15 ----
        if (valid) {
            unsigned a[8][4];
            load_a(a, xs, PITCH, lane);   // rows 8..15 read xc rows 0..7 (discarded)
            gemm_tile<0, true>(a, s_bw, s_b + 640, warp * 16,     xc + 8 * PITCH, PITCH, 0, 0, lane);
            gemm_tile<0, true>(a, s_bw, s_b + 640, warp * 16 + 8, xc + 8 * PITCH, PITCH, 0, 0, lane);
        }
        __syncthreads();

        // ---- P2: qkv = xc @ ipw^T + ipb ----
        if (valid) {
            unsigned a[8][4];
            load_a(a, xc, PITCH, lane);
            #pragma unroll
            for (int nt = 0; nt < 6; nt++)
                gemm_tile<0, false>(a, s_ipw, s_b, warp * 48 + nt * 8, qv, QPITCH, 0, 0, lane);
        }
        __syncthreads();

        // ---- P3: attention, 128 threads: (head, query, key-half) ----
        if (valid) {
            int hh = st >> 5, q = (st >> 1) & 15, half = st & 1;
            const float4* qrow = (const float4*)(qv + q * QPITCH + hh * 16);
            float4 qr0 = qrow[0], qr1 = qrow[1], qr2 = qrow[2], qr3 = qrow[3];
            float sc[8], m = -1e30f;
            #pragma unroll
            for (int kk = 0; kk < 8; kk++) {
                int k = half * 8 + kk;
                const float4* kr = (const float4*)(qv + k * QPITCH + 64 + hh * 16);
                float4 k0 = kr[0], k1 = kr[1], k2 = kr[2], k3 = kr[3];
                float a0 = qr0.x * k0.x + qr0.y * k0.y + qr0.z * k0.z + qr0.w * k0.w;
                float a1 = qr1.x * k1.x + qr1.y * k1.y + qr1.z * k1.z + qr1.w * k1.w;
                float a2 = qr2.x * k2.x + qr2.y * k2.y + qr2.z * k2.z + qr2.w * k2.w;
                float a3 = qr3.x * k3.x + qr3.y * k3.y + qr3.z * k3.z + qr3.w * k3.w;
                float s = ((a0 + a1) + (a2 + a3)) * 0.25f;
                sc[kk] = s; m = fmaxf(m, s);
            }
            m = fmaxf(m, __shfl_xor_sync(0xffffffffu, m, 1));
            float ssum = 0.f;
            #pragma unroll
            for (int kk = 0; kk < 8; kk++) { sc[kk] = __expf(sc[kk] - m); ssum += sc[kk]; }
            ssum += __shfl_xor_sync(0xffffffffu, ssum, 1);
            float rs = 1.f / ssum;
            float w16[16];
            #pragma unroll
            for (int kk = 0; kk < 8; kk++) {
                float o = __shfl_xor_sync(0xffffffffu, sc[kk], 1);
                w16[half * 8 + kk] = sc[kk];
                w16[(1 - half) * 8 + kk] = o;
            }
            // AV over dims [half*8, half*8+8)
            float4 o0 = make_float4(0.f,0.f,0.f,0.f), o1 = o0;
            #pragma unroll
            for (int k = 0; k < 16; k++) {
                float a = w16[k];
                const float4* vr = (const float4*)(qv + k * QPITCH + 128 + hh * 16 + half * 8);
                float4 v0 = vr[0], v1 = vr[1];
                o0.x = fmaf(a, v0.x, o0.x); o0.y = fmaf(a, v0.y, o0.y);
                o0.z = fmaf(a, v0.z, o0.z); o0.w = fmaf(a, v0.w, o0.w);
                o1.x = fmaf(a, v1.x, o1.x); o1.y = fmaf(a, v1.y, o1.y);
                o1.z = fmaf(a, v1.z, o1.z); o1.w = fmaf(a, v1.w, o1.w);
            }
            float4* dst = (float4*)(ao + q * PITCH + hh * 16 + half * 8);
            dst[0] = make_float4(o0.x*rs, o0.y*rs, o0.z*rs, o0.w*rs);
            dst[1] = make_float4(o1.x*rs, o1.y*rs, o1.z*rs, o1.w*rs);
        }
        __syncthreads();

        // ---- P4: out_proj + residual -> qv ----
        if (valid) {
            unsigned a[8][4];
            load_a(a, ao, PITCH, lane);
            gemm_tile<2, false>(a, s_opw, s_b + 192, warp * 16,     qv, QPITCH, xc, PITCH, lane);
            gemm_tile<2, false>(a, s_opw, s_b + 192, warp * 16 + 8, qv, QPITCH, xc, PITCH, lane);
        }
        __syncthreads();

        // ---- P5: LayerNorm1 -> xc ----
        if (valid && st < 16) {
            const float4* row = (const float4*)(qv + st * QPITCH);
            float mu = 0.f;
            #pragma unroll
            for (int i = 0; i < 16; i++) { float4 r4 = row[i]; mu += (r4.x + r4.y) + (r4.z + r4.w); }
            mu *= 0.015625f;
            float v = 0.f;
            #pragma unroll
            for (int i = 0; i < 16; i++) {
                float4 r4 = row[i];
                float t0 = r4.x - mu, t1 = r4.y - mu, t2 = r4.z - mu, t3 = r4.w - mu;
                v = fmaf(t0, t0, v); v = fmaf(t1, t1, v);
                v = fmaf(t2, t2, v); v = fmaf(t3, t3, v);
            }
            stt[st] = mu;
            stt[16 + st] = rsqrtf(v * 0.015625f + 1e-5f);
        }
        __syncthreads();
        if (valid) {
            #pragma unroll
            for (int i = 0; i < 8; i++) {
                int idx = st * 8 + i;
                int s = idx >> 6, d = idx & 63;
                xc[s * PITCH + d] =
                    (qv[s * QPITCH + d] - stt[s]) * stt[16 + s] * s_b[384 + d] + s_b[448 + d];
            }
        }
        __syncthreads();

        // ---- P6: FF1 + relu -> ao ----
        if (valid) {
            unsigned a[8][4];
            load_a(a, xc, PITCH, lane);
            gemm_tile<1, false>(a, s_w1, s_b + 256, warp * 16,     ao, PITCH, 0, 0, lane);
            gemm_tile<1, false>(a, s_w1, s_b + 256, warp * 16 + 8, ao, PITCH, 0, 0, lane);
        }
        __syncthreads();

        // ---- P7: FF2 + residual -> qv ----
        if (valid) {
            unsigned a[8][4];
            load_a(a, ao, PITCH, lane);
            gemm_tile<2, false>(a, s_w2, s_b + 320, warp * 16,     qv, QPITCH, xc, PITCH, lane);
            gemm_tile<2, false>(a, s_w2, s_b + 320, warp * 16 + 8, qv, QPITCH, xc, PITCH, lane);
        }
        __syncthreads();

        // ---- P8: LayerNorm2 (tokens 0..7) + scaled atomic scatter ----
        if (valid && st < 8) {
            const float4* row = (const float4*)(qv + st * QPITCH);
            float mu = 0.f;
            #pragma unroll
            for (int i = 0; i < 16; i++) { float4 r4 = row[i]; mu += (r4.x + r4.y) + (r4.z + r4.w); }
            mu *= 0.015625f;
            float v = 0.f;
            #pragma unroll
            for (int i = 0; i < 16; i++) {
                float4 r4 = row[i];
                float t0 = r4.x - mu, t1 = r4.y - mu, t2 = r4.z - mu, t3 = r4.w - mu;
                v = fmaf(t0, t0, v); v = fmaf(t1, t1, v);
                v = fmaf(t2, t2, v); v = fmaf(t3, t3, v);
            }
            stt[st] = mu;
            stt[16 + st] = rsqrtf(v * 0.015625f + 1e-5f);
        }
        __syncthreads();
        if (valid) {
            int r = st >> 4, dbase = (st & 15) << 2;
            float mu = stt[r], rstd = stt[16 + r];
            float* dst = hout + (size_t)tgt * 512 + r * 64 + dbase;
            #pragma unroll
            for (int t = 0; t < 4; t++) {
                int d = dbase + t;
                float val = (qv[r * QPITCH + d] - mu) * rstd * s_b[512 + d] + s_b[576 + d];
                atomicAdd(dst + t, val * ic);
            }
        }
        __syncthreads();
    }
}

// ---------------- output head ----------------
__global__ void out_kernel(const float* __restrict__ ow,
                           const float* __restrict__ ob,
                           float* __restrict__ out) {
    __shared__ float shs[8][64];
    int w = threadIdx.x >> 5, lane = threadIdx.x & 31;
    int n = blockIdx.x * 8 + w;
    if (n >= NN) return;
    const float* hr = g_hA + (size_t)n * 512;
    float lo = 0.f, hi = 0.f;
    #pragma unroll
    for (int c = 0; c < 8; c++) { lo += hr[c * 64 + lane]; hi += hr[c * 64 + 32 + lane]; }
    shs[w][lane] = lo; shs[w][lane + 32] = hi;
    __syncwarp();
    float z = -1e30f;
    if (lane < 16) {
        float acc = 8.f * ob[lane];
        const float* wr = ow + lane * 64;
        #pragma unroll
        for (int d = 0; d < 64; d++) acc = fmaf(shs[w][d], wr[d], acc);
        z = acc;
    }
    float m = z;
    #pragma unroll
    for (int off = 8; off; off >>= 1) m = fmaxf(m, __shfl_xor_sync(0xffffffffu, m, off, 16));
    float p = __expf(z - m);
    float s = p;
    #pragma unroll
    for (int off = 8; off; off >>= 1) s += __shfl_xor_sync(0xffffffffu, s, off, 16);
    if (lane < 16) out[n * 16 + lane] = p / s;
}

// ---------------- launch ----------------
extern "C" void kernel_launch(void* const* d_in, const int* in_sizes, int n_in,
                              void* d_out, int out_size) {
    const float* x    = (const float*)d_in[0];
    const int*   ei   = (const int*)d_in[1];
    const float* numw = (const float*)d_in[2];
    const float* numb = (const float*)d_in[3];
    const float* bpw  = (const float*)d_in[4];
    const float* bpb  = (const float*)d_in[5];
    const float* ipw  = (const float*)d_in[6];
    const float* ipb  = (const float*)d_in[7];
    const float* opw  = (const float*)d_in[8];
    const float* opb  = (const float*)d_in[9];
    const float* g1   = (const float*)d_in[10];
    const float* b1   = (const float*)d_in[11];
    const float* g2   = (const float*)d_in[12];
    const float* b2   = (const float*)d_in[13];
    const float* w1   = (const float*)d_in[14];
    const float* fb1  = (const float*)d_in[15];
    const float* w2   = (const float*)d_in[16];
    const float* fb2  = (const float*)d_in[17];
    const float* ow   = (const float*)d_in[18];
    const float* ob   = (const float*)d_in[19];
    float* out = (float*)d_out;

    const int SMEM_BYTES = (192 * PITCH + 4 * 64 * PITCH + 704 + 4 * 5888) * 4;
    cudaFuncSetAttribute(edge_kernel, cudaFuncAttributeMaxDynamicSharedMemorySize, SMEM_BYTES);

    int dev = 0, sms = 148;
    cudaGetDevice(&dev);
    cudaDeviceGetAttribute(&sms, cudaDevAttrMultiProcessorCount, dev);

    init_any_kernel<<<1, 1>>>();
    detect_kernel<<<256, 256>>>(ei);
    embed_kernel<<<(NN * 512 + 255) / 256, 256>>>(x, numw, numb);
    zero_cnt_kernel<<<(NN + 255) / 256, 256>>>();
    count_kernel<<<(EE + 255) / 256, 256>>>(ei);
    fin_cnt_kernel<<<(NN + 255) / 256, 256>>>();

    // layer 0: A -> B
    zero_h_kernel<<<(NN * 128 + 255) / 256, 256>>>(1);
    edge_kernel<<<sms, 512, SMEM_BYTES>>>(ei, 0,
        bpw, bpb, ipw, ipb, opw, opb, g1, b1, g2, b2, w1, fb1, w2, fb2);

    // layer 1: B -> A
    zero_h_kernel<<<(NN * 128 + 255) / 256, 256>>>(0);
    edge_kernel<<<sms, 512, SMEM_BYTES>>>(ei, 1,
        bpw + 64 * 64, bpb + 64, ipw + 192 * 64, ipb + 192, opw + 64 * 64, opb + 64,
        g1 + 64, b1 + 64, g2 + 64, b2 + 64,
        w1 + 64 * 64, fb1 + 64, w2 + 64 * 64, fb2 + 64);

    out_kernel<<<(NN + 7) / 8, 256>>>(ow, ob, out);
}

// round 3
// speedup vs baseline: 2.7392x; 1.2940x over previous
#include <cuda_runtime.h>

#define NN 50000
#define CC 8
#define DD 64
#define EE 100000
#define PITCH 68      // padded row for 64-wide matrices
#define QPITCH 196    // padded row for qkv (192 cols)

// -------- scratch (device globals: allocation-free) --------
__device__ float g_hA[(size_t)NN * 512];
__device__ float g_hB[(size_t)NN * 512];
__device__ float g_inv[NN];
__device__ int   g_any;

// ---------------- setup kernels (packed so edge_kernel is launch #6) ----------------

// #1: init g_any, zero g_inv, zero g_hB
__global__ void setup0_kernel() {
    size_t i = (size_t)blockIdx.x * blockDim.x + threadIdx.x;
    if (i == 0) g_any = 0;
    if (i < NN) g_inv[i] = 0.f;
    if (i < (size_t)NN * 128) ((float4*)g_hB)[i] = make_float4(0.f, 0.f, 0.f, 0.f);
}

// #2: int64 vs int32 detection (odd words of row 0 all zero => int64)
__global__ void detect_kernel(const int* __restrict__ ei) {
    int i = blockIdx.x * blockDim.x + threadIdx.x;
    int v = 0;
    for (int k = i; k < EE; k += gridDim.x * blockDim.x) v |= ei[2 * k + 1];
    if (v) atomicOr(&g_any, 1);
}

// #3: column embedding into g_hA
__global__ void embed_kernel(const float* __restrict__ x,
                             const float* __restrict__ nw,
                             const float* __restrict__ nb) {
    int i = blockIdx.x * blockDim.x + threadIdx.x;
    if (i < NN * 512) {
        int n = i >> 9;
        int r = i & 511;
        g_hA[i] = x[n * 8 + (r >> 6)] * nw[r] + nb[r];
    }
}

// #4: in-degree histogram
__global__ void count_kernel(const int* __restrict__ ei) {
    int e = blockIdx.x * blockDim.x + threadIdx.x;
    if (e < EE) {
        int is64 = (g_any == 0);
        int t = is64 ? ei[2 * (EE + e)] : ei[EE + e];
        atomicAdd(&g_inv[t], 1.0f);
    }
}

// #5: reciprocal of clipped counts
__global__ void fin_cnt_kernel() {
    int i = blockIdx.x * blockDim.x + threadIdx.x;
    if (i < NN) g_inv[i] = 1.0f / fmaxf(g_inv[i], 1.0f);
}

// zero g_hA between layers
__global__ void zeroA_kernel() {
    size_t i = (size_t)blockIdx.x * blockDim.x + threadIdx.x;
    if (i < (size_t)NN * 128) ((float4*)g_hA)[i] = make_float4(0.f, 0.f, 0.f, 0.f);
}

// ---------------- tf32 mma helpers ----------------

__device__ __forceinline__ unsigned f2tf(float x) {
    unsigned r;
    asm("cvt.rna.tf32.f32 %0, %1;" : "=r"(r) : "f"(x));
    return r;
}

__device__ __forceinline__ void mma_tf32(float& c0, float& c1, float& c2, float& c3,
                                         unsigned a0, unsigned a1, unsigned a2, unsigned a3,
                                         unsigned b0, unsigned b1) {
    asm volatile(
        "mma.sync.aligned.m16n8k8.row.col.f32.tf32.tf32.f32 "
        "{%0,%1,%2,%3}, {%4,%5,%6,%7}, {%8,%9}, {%0,%1,%2,%3};\n"
        : "+f"(c0), "+f"(c1), "+f"(c2), "+f"(c3)
        : "r"(a0), "r"(a1), "r"(a2), "r"(a3), "r"(b0), "r"(b1));
}

__device__ __forceinline__ void load_a(unsigned a[8][4], const float* __restrict__ X,
                                       int xp, int lane) {
    int row = lane >> 2, kc = lane & 3;
    const float* p0 = X + row * xp + kc;
    const float* p1 = X + (row + 8) * xp + kc;
    #pragma unroll
    for (int kb = 0; kb < 8; kb++) {
        a[kb][0] = f2tf(p0[kb * 8]);
        a[kb][1] = f2tf(p1[kb * 8]);
        a[kb][2] = f2tf(p0[kb * 8 + 4]);
        a[kb][3] = f2tf(p1[kb * 8 + 4]);
    }
}

// EPI: 0 plain, 1 relu, 2 add residual R ; ROWS8: only rows 0..7 stored
template<int EPI, bool ROWS8>
__device__ __forceinline__ void gemm_tile(const unsigned a[8][4],
                                          const float* __restrict__ W,
                                          const float* __restrict__ bias,
                                          int jbase,
                                          float* __restrict__ C, int cp,
                                          const float* __restrict__ R, int rp,
                                          int lane) {
    int g = lane >> 2, tg = lane & 3;
    int col0 = jbase + 2 * tg;
    float2 bb = *(const float2*)(bias + col0);
    float c0 = bb.x, c1 = bb.y, c2 = bb.x, c3 = bb.y;
    const float* wr = W + (jbase + g) * PITCH;
    #pragma unroll
    for (int kb = 0; kb < 8; kb++) {
        unsigned b0 = __float_as_uint(wr[kb * 8 + tg]);
        unsigned b1 = __float_as_uint(wr[kb * 8 + tg + 4]);
        mma_tf32(c0, c1, c2, c3, a[kb][0], a[kb][1], a[kb][2], a[kb][3], b0, b1);
    }
    if (EPI == 2) {
        float2 r0 = *(const float2*)(R + g * rp + col0);
        float2 r1 = *(const float2*)(R + (g + 8) * rp + col0);
        c0 += r0.x; c1 += r0.y; c2 += r1.x; c3 += r1.y;
    }
    if (EPI == 1) {
        c0 = fmaxf(c0, 0.f); c1 = fmaxf(c1, 0.f);
        c2 = fmaxf(c2, 0.f); c3 = fmaxf(c3, 0.f);
    }
    *(float2*)(C + g * cp + col0) = make_float2(c0, c1);
    if (!ROWS8) *(float2*)(C + (g + 8) * cp + col0) = make_float2(c2, c3);
}

// ---------------- main per-edge transformer kernel ----------------

#define SUBBAR() asm volatile("bar.sync %0, 128;" :: "r"(sub + 1) : "memory")

__global__ void __launch_bounds__(512, 1)
edge_kernel(const int* __restrict__ ei, int dir,
            const float* __restrict__ bpw, const float* __restrict__ bpb,
            const float* __restrict__ ipw, const float* __restrict__ ipb,
            const float* __restrict__ opw, const float* __restrict__ opb,
            const float* __restrict__ ln1g, const float* __restrict__ ln1b,
            const float* __restrict__ ln2g, const float* __restrict__ ln2b,
            const float* __restrict__ w1,  const float* __restrict__ fb1,
            const float* __restrict__ w2,  const float* __restrict__ fb2) {
    extern __shared__ float sm[];
    float* s_ipw = sm;                          // 192*68
    float* s_opw = s_ipw + 192 * PITCH;         // 64*68
    float* s_w1  = s_opw + 64 * PITCH;
    float* s_w2  = s_w1  + 64 * PITCH;
    float* s_bw  = s_w2  + 64 * PITCH;
    float* s_b   = s_bw  + 64 * PITCH;          // 704 floats biases/ln
    float* s_act = s_b + 704;

    const float* hin  = dir ? g_hB : g_hA;
    float*       hout = dir ? g_hA : g_hB;

    const int tid = threadIdx.x;

    // ---- stage weights once, pre-rounded to tf32 ----
    for (int i = tid; i < 192 * 64; i += 512)
        s_ipw[(i >> 6) * PITCH + (i & 63)] = __uint_as_float(f2tf(ipw[i]));
    for (int i = tid; i < 64 * 64; i += 512) {
        int r = (i >> 6) * PITCH + (i & 63);
        s_opw[r] = __uint_as_float(f2tf(opw[i]));
        s_w1[r]  = __uint_as_float(f2tf(w1[i]));
        s_w2[r]  = __uint_as_float(f2tf(w2[i]));
        s_bw[r]  = __uint_as_float(f2tf(bpw[i]));
    }
    for (int i = tid; i < 192; i += 512) s_b[i] = ipb[i];
    if (tid < 64) {
        s_b[192 + tid] = opb[tid];  s_b[256 + tid] = fb1[tid];
        s_b[320 + tid] = fb2[tid];  s_b[384 + tid] = ln1g[tid];
        s_b[448 + tid] = ln1b[tid]; s_b[512 + tid] = ln2g[tid];
        s_b[576 + tid] = ln2b[tid]; s_b[640 + tid] = bpb[tid];
    }
    __syncthreads();

    const int sub  = tid >> 7;     // 0..3 edge slot
    const int st   = tid & 127;
    const int warp = st >> 5;
    const int lane = st & 31;
    float* xs  = s_act + sub * 5888;       // 8*68
    float* xc  = xs + 8 * PITCH;           // 16*68
    float* qv  = xc + 16 * PITCH;          // 16*196
    float* ao  = qv + 16 * QPITCH;         // 16*68

    const int is64 = (g_any == 0);
    const int r0 = st >> 4, d0 = (st & 15) << 2;   // gather slice owned by this thread
    const int stride4 = gridDim.x * 4;

    // ---- prologue prefetch ----
    bool pv; int ptgt = 0; float pic = 0.f;
    float4 pvi = make_float4(0,0,0,0), pvj = pvi;
    {
        int e = blockIdx.x * 4 + sub;
        pv = e < EE;
        if (pv) {
            int src = is64 ? ei[2 * e]        : ei[e];
            ptgt    = is64 ? ei[2 * (EE + e)] : ei[EE + e];
            pic = g_inv[ptgt];
            pvi = *(const float4*)(hin + (size_t)ptgt * 512 + r0 * 64 + d0);
            pvj = *(const float4*)(hin + (size_t)src  * 512 + r0 * 64 + d0);
        }
    }

    for (int base = blockIdx.x * 4; base < EE; base += stride4) {
        const bool valid = pv;
        const int  tgt = ptgt;
        const float ic = pic;

        // ---- P0: commit prefetched gather to smem ----
        if (valid) {
            *(float4*)(xc + r0 * PITCH + d0) = pvi;
            *(float4*)(xs + r0 * PITCH + d0) = pvj;
        }
        SUBBAR();

        // ---- prefetch next iteration (overlaps all compute below) ----
        {
            int en = base + stride4 + sub;
            pv = en < EE;
            if (pv) {
                int src = is64 ? ei[2 * en]        : ei[en];
                ptgt    = is64 ? ei[2 * (EE + en)] : ei[EE + en];
                pic = g_inv[ptgt];
                pvi = *(const float4*)(hin + (size_t)ptgt * 512 + r0 * 64 + d0);
                pvj = *(const float4*)(hin + (size_t)src  * 512 + r0 * 64 + d0);
            }
        }

        // ---- P1: bproj -> xc rows 8..15 ----
        if (valid) {
            unsigned a[8][4];
            load_a(a, xs, PITCH, lane);
            gemm_tile<0, true>(a, s_bw, s_b + 640, warp * 16,     xc + 8 * PITCH, PITCH, 0, 0, lane);
            gemm_tile<0, true>(a, s_bw, s_b + 640, warp * 16 + 8, xc + 8 * PITCH, PITCH, 0, 0, lane);
        }
        SUBBAR();

        // ---- P2: qkv ----
        if (valid) {
            unsigned a[8][4];
            load_a(a, xc, PITCH, lane);
            #pragma unroll
            for (int nt = 0; nt < 6; nt++)
                gemm_tile<0, false>(a, s_ipw, s_b, warp * 48 + nt * 8, qv, QPITCH, 0, 0, lane);
        }
        SUBBAR();

        // ---- P3: attention ----
        if (valid) {
            int hh = st >> 5, q = (st >> 1) & 15, half = st & 1;
            const float4* qrow = (const float4*)(qv + q * QPITCH + hh * 16);
            float4 qr0 = qrow[0], qr1 = qrow[1], qr2 = qrow[2], qr3 = qrow[3];
            float sc[8], m = -1e30f;
            #pragma unroll
            for (int kk = 0; kk < 8; kk++) {
                int k = half * 8 + kk;
                const float4* kr = (const float4*)(qv + k * QPITCH + 64 + hh * 16);
                float4 k0 = kr[0], k1 = kr[1], k2 = kr[2], k3 = kr[3];
                float a0 = qr0.x * k0.x + qr0.y * k0.y + qr0.z * k0.z + qr0.w * k0.w;
                float a1 = qr1.x * k1.x + qr1.y * k1.y + qr1.z * k1.z + qr1.w * k1.w;
                float a2 = qr2.x * k2.x + qr2.y * k2.y + qr2.z * k2.z + qr2.w * k2.w;
                float a3 = qr3.x * k3.x + qr3.y * k3.y + qr3.z * k3.z + qr3.w * k3.w;
                float s = ((a0 + a1) + (a2 + a3)) * 0.25f;
                sc[kk] = s; m = fmaxf(m, s);
            }
            m = fmaxf(m, __shfl_xor_sync(0xffffffffu, m, 1));
            float ssum = 0.f;
            #pragma unroll
            for (int kk = 0; kk < 8; kk++) { sc[kk] = __expf(sc[kk] - m); ssum += sc[kk]; }
            ssum += __shfl_xor_sync(0xffffffffu, ssum, 1);
            float rs = 1.f / ssum;
            float w16[16];
            #pragma unroll
            for (int kk = 0; kk < 8; kk++) {
                float o = __shfl_xor_sync(0xffffffffu, sc[kk], 1);
                w16[half * 8 + kk] = sc[kk];
                w16[(1 - half) * 8 + kk] = o;
            }
            float4 o0 = make_float4(0.f,0.f,0.f,0.f), o1 = o0;
            #pragma unroll
            for (int k = 0; k < 16; k++) {
                float a = w16[k];
                const float4* vr = (const float4*)(qv + k * QPITCH + 128 + hh * 16 + half * 8);
                float4 v0 = vr[0], v1 = vr[1];
                o0.x = fmaf(a, v0.x, o0.x); o0.y = fmaf(a, v0.y, o0.y);
                o0.z = fmaf(a, v0.z, o0.z); o0.w = fmaf(a, v0.w, o0.w);
                o1.x = fmaf(a, v1.x, o1.x); o1.y = fmaf(a, v1.y, o1.y);
                o1.z = fmaf(a, v1.z, o1.z); o1.w = fmaf(a, v1.w, o1.w);
            }
            float4* dst = (float4*)(ao + q * PITCH + hh * 16 + half * 8);
            dst[0] = make_float4(o0.x*rs, o0.y*rs, o0.z*rs, o0.w*rs);
            dst[1] = make_float4(o1.x*rs, o1.y*rs, o1.z*rs, o1.w*rs);
        }
        SUBBAR();

        // ---- P4: out_proj + residual -> qv ----
        if (valid) {
            unsigned a[8][4];
            load_a(a, ao, PITCH, lane);
            gemm_tile<2, false>(a, s_opw, s_b + 192, warp * 16,     qv, QPITCH, xc, PITCH, lane);
            gemm_tile<2, false>(a, s_opw, s_b + 192, warp * 16 + 8, qv, QPITCH, xc, PITCH, lane);
        }
        SUBBAR();

        // ---- LN1 (8 threads/row, shfl reduce) -> xc ----
        if (valid) {
            int row = st >> 3, part = st & 7, c0 = part * 8;
            const float4* p = (const float4*)(qv + row * QPITCH + c0);
            float4 u0 = p[0], u1 = p[1];
            float s = (u0.x + u0.y) + (u0.z + u0.w) + (u1.x + u1.y) + (u1.z + u1.w);
            s += __shfl_xor_sync(0xffffffffu, s, 1);
            s += __shfl_xor_sync(0xffffffffu, s, 2);
            s += __shfl_xor_sync(0xffffffffu, s, 4);
            float mu = s * 0.015625f;
            float t0 = u0.x - mu, t1 = u0.y - mu, t2 = u0.z - mu, t3 = u0.w - mu;
            float t4 = u1.x - mu, t5 = u1.y - mu, t6 = u1.z - mu, t7 = u1.w - mu;
            float v = t0*t0 + t1*t1 + t2*t2 + t3*t3 + t4*t4 + t5*t5 + t6*t6 + t7*t7;
            v += __shfl_xor_sync(0xffffffffu, v, 1);
            v += __shfl_xor_sync(0xffffffffu, v, 2);
            v += __shfl_xor_sync(0xffffffffu, v, 4);
            float rstd = rsqrtf(v * 0.015625f + 1e-5f);
            const float4 g0 = *(const float4*)(s_b + 384 + c0);
            const float4 g1 = *(const float4*)(s_b + 384 + c0 + 4);
            const float4 bb0 = *(const float4*)(s_b + 448 + c0);
            const float4 bb1 = *(const float4*)(s_b + 448 + c0 + 4);
            float4 o0, o1;
            o0.x = t0 * rstd * g0.x + bb0.x; o0.y = t1 * rstd * g0.y + bb0.y;
            o0.z = t2 * rstd * g0.z + bb0.z; o0.w = t3 * rstd * g0.w + bb0.w;
            o1.x = t4 * rstd * g1.x + bb1.x; o1.y = t5 * rstd * g1.y + bb1.y;
            o1.z = t6 * rstd * g1.z + bb1.z; o1.w = t7 * rstd * g1.w + bb1.w;
            *(float4*)(xc + row * PITCH + c0) = o0;
            *(float4*)(xc + row * PITCH + c0 + 4) = o1;
        }
        SUBBAR();

        // ---- P6: FF1 + relu -> ao ----
        if (valid) {
            unsigned a[8][4];
            load_a(a, xc, PITCH, lane);
            gemm_tile<1, false>(a, s_w1, s_b + 256, warp * 16,     ao, PITCH, 0, 0, lane);
            gemm_tile<1, false>(a, s_w1, s_b + 256, warp * 16 + 8, ao, PITCH, 0, 0, lane);
        }
        SUBBAR();

        // ---- P7: FF2 + residual -> qv ----
        if (valid) {
            unsigned a[8][4];
            load_a(a, ao, PITCH, lane);
            gemm_tile<2, false>(a, s_w2, s_b + 320, warp * 16,     qv, QPITCH, xc, PITCH, lane);
            gemm_tile<2, false>(a, s_w2, s_b + 320, warp * 16 + 8, qv, QPITCH, xc, PITCH, lane);
        }
        SUBBAR();

        // ---- LN2 (rows 0..7, 16 threads/row) fused with scaled atomic scatter ----
        if (valid) {
            int row = st >> 4, part = st & 15, c0 = part * 4;
            float4 u = *(const float4*)(qv + row * QPITCH + c0);
            float s = (u.x + u.y) + (u.z + u.w);
            s += __shfl_xor_sync(0xffffffffu, s, 1);
            s += __shfl_xor_sync(0xffffffffu, s, 2);
            s += __shfl_xor_sync(0xffffffffu, s, 4);
            s += __shfl_xor_sync(0xffffffffu, s, 8);
            float mu = s * 0.015625f;
            float t0 = u.x - mu, t1 = u.y - mu, t2 = u.z - mu, t3 = u.w - mu;
            float v = t0*t0 + t1*t1 + t2*t2 + t3*t3;
            v += __shfl_xor_sync(0xffffffffu, v, 1);
            v += __shfl_xor_sync(0xffffffffu, v, 2);
            v += __shfl_xor_sync(0xffffffffu, v, 4);
            v += __shfl_xor_sync(0xffffffffu, v, 8);
            float rstd = rsqrtf(v * 0.015625f + 1e-5f);
            const float4 gg = *(const float4*)(s_b + 512 + c0);
            const float4 bb = *(const float4*)(s_b + 576 + c0);
            float* dst = hout + (size_t)tgt * 512 + row * 64 + c0;
            atomicAdd(dst + 0, (t0 * rstd * gg.x + bb.x) * ic);
            atomicAdd(dst + 1, (t1 * rstd * gg.y + bb.y) * ic);
            atomicAdd(dst + 2, (t2 * rstd * gg.z + bb.z) * ic);
            atomicAdd(dst + 3, (t3 * rstd * gg.w + bb.w) * ic);
        }
        // no barrier needed: next write to qv is P2 (two barriers away);
        // loop-top STS touches xc rows 0..7 / xs only (last read before last bar).
    }
}

// ---------------- output head ----------------
__global__ void out_kernel(const float* __restrict__ ow,
                           const float* __restrict__ ob,
                           float* __restrict__ out) {
    __shared__ float shs[8][64];
    int w = threadIdx.x >> 5, lane = threadIdx.x & 31;
    int n = blockIdx.x * 8 + w;
    if (n >= NN) return;
    const float* hr = g_hA + (size_t)n * 512;
    float lo = 0.f, hi = 0.f;
    #pragma unroll
    for (int c = 0; c < 8; c++) { lo += hr[c * 64 + lane]; hi += hr[c * 64 + 32 + lane]; }
    shs[w][lane] = lo; shs[w][lane + 32] = hi;
    __syncwarp();
    float z = -1e30f;
    if (lane < 16) {
        float acc = 8.f * ob[lane];
        const float* wr = ow + lane * 64;
        #pragma unroll
        for (int d = 0; d < 64; d++) acc = fmaf(shs[w][d], wr[d], acc);
        z = acc;
    }
    float m = z;
    #pragma unroll
    for (int off = 8; off; off >>= 1) m = fmaxf(m, __shfl_xor_sync(0xffffffffu, m, off, 16));
    float p = __expf(z - m);
    float s = p;
    #pragma unroll
    for (int off = 8; off; off >>= 1) s += __shfl_xor_sync(0xffffffffu, s, off, 16);
    if (lane < 16) out[n * 16 + lane] = p / s;
}

// ---------------- launch ----------------
extern "C" void kernel_launch(void* const* d_in, const int* in_sizes, int n_in,
                              void* d_out, int out_size) {
    const float* x    = (const float*)d_in[0];
    const int*   ei   = (const int*)d_in[1];
    const float* numw = (const float*)d_in[2];
    const float* numb = (const float*)d_in[3];
    const float* bpw  = (const float*)d_in[4];
    const float* bpb  = (const float*)d_in[5];
    const float* ipw  = (const float*)d_in[6];
    const float* ipb  = (const float*)d_in[7];
    const float* opw  = (const float*)d_in[8];
    const float* opb  = (const float*)d_in[9];
    const float* g1   = (const float*)d_in[10];
    const float* b1   = (const float*)d_in[11];
    const float* g2   = (const float*)d_in[12];
    const float* b2   = (const float*)d_in[13];
    const float* w1   = (const float*)d_in[14];
    const float* fb1  = (const float*)d_in[15];
    const float* w2   = (const float*)d_in[16];
    const float* fb2  = (const float*)d_in[17];
    const float* ow   = (const float*)d_in[18];
    const float* ob   = (const float*)d_in[19];
    float* out = (float*)d_out;

    const int SMEM_BYTES = (192 * PITCH + 4 * 64 * PITCH + 704 + 4 * 5888) * 4;
    cudaFuncSetAttribute(edge_kernel, cudaFuncAttributeMaxDynamicSharedMemorySize, SMEM_BYTES);

    int dev = 0, sms = 148;
    cudaGetDevice(&dev);
    cudaDeviceGetAttribute(&sms, cudaDevAttrMultiProcessorCount, dev);

    // launches 1..5 (setup), 6 = edge_kernel (ncu -s 5 -c 1 capture slot)
    setup0_kernel<<<(NN * 128 + 255) / 256, 256>>>();
    detect_kernel<<<256, 256>>>(ei);
    embed_kernel<<<(NN * 512 + 255) / 256, 256>>>(x, numw, numb);
    count_kernel<<<(EE + 255) / 256, 256>>>(ei);
    fin_cnt_kernel<<<(NN + 255) / 256, 256>>>();

    // layer 0: A -> B
    edge_kernel<<<sms, 512, SMEM_BYTES>>>(ei, 0,
        bpw, bpb, ipw, ipb, opw, opb, g1, b1, g2, b2, w1, fb1, w2, fb2);

    // layer 1: B -> A
    zeroA_kernel<<<(NN * 128 + 255) / 256, 256>>>();
    edge_kernel<<<sms, 512, SMEM_BYTES>>>(ei, 1,
        bpw + 64 * 64, bpb + 64, ipw + 192 * 64, ipb + 192, opw + 64 * 64, opb + 64,
        g1 + 64, b1 + 64, g2 + 64, b2 + 64,
        w1 + 64 * 64, fb1 + 64, w2 + 64 * 64, fb2 + 64);

    out_kernel<<<(NN + 7) / 8, 256>>>(ow, ob, out);
}

// round 4
// speedup vs baseline: 3.0440x; 1.1113x over previous
#include <cuda_runtime.h>

#define NN 50000
#define CC 8
#define DD 64
#define EE 100000
#define PITCH 68      // padded row for 64-wide matrices
#define QPITCH 196    // padded row for qkv (192 cols)

// -------- scratch (device globals: allocation-free) --------
__device__ float g_hA[(size_t)NN * 512];
__device__ float g_hB[(size_t)NN * 512];
__device__ float g_inv[NN];
__device__ int   g_any;

// ---------------- setup kernels ----------------

__global__ void setup0_kernel() {
    size_t i = (size_t)blockIdx.x * blockDim.x + threadIdx.x;
    if (i == 0) g_any = 0;
    if (i < NN) g_inv[i] = 0.f;
    if (i < (size_t)NN * 128) ((float4*)g_hB)[i] = make_float4(0.f, 0.f, 0.f, 0.f);
}

__global__ void detect_kernel(const int* __restrict__ ei) {
    int i = blockIdx.x * blockDim.x + threadIdx.x;
    int v = 0;
    for (int k = i; k < EE; k += gridDim.x * blockDim.x) v |= ei[2 * k + 1];
    if (v) atomicOr(&g_any, 1);
}

__global__ void embed_kernel(const float* __restrict__ x,
                             const float* __restrict__ nw,
                             const float* __restrict__ nb) {
    int i = blockIdx.x * blockDim.x + threadIdx.x;
    if (i < NN * 512) {
        int n = i >> 9;
        int r = i & 511;
        g_hA[i] = x[n * 8 + (r >> 6)] * nw[r] + nb[r];
    }
}

__global__ void count_kernel(const int* __restrict__ ei) {
    int e = blockIdx.x * blockDim.x + threadIdx.x;
    if (e < EE) {
        int is64 = (g_any == 0);
        int t = is64 ? ei[2 * (EE + e)] : ei[EE + e];
        atomicAdd(&g_inv[t], 1.0f);
    }
}

__global__ void fin_cnt_kernel() {
    int i = blockIdx.x * blockDim.x + threadIdx.x;
    if (i < NN) g_inv[i] = 1.0f / fmaxf(g_inv[i], 1.0f);
}

__global__ void zeroA_kernel() {
    size_t i = (size_t)blockIdx.x * blockDim.x + threadIdx.x;
    if (i < (size_t)NN * 128) ((float4*)g_hA)[i] = make_float4(0.f, 0.f, 0.f, 0.f);
}

// ---------------- tf32 mma helpers ----------------

__device__ __forceinline__ unsigned f2tf(float x) {
    unsigned r;
    asm("cvt.rna.tf32.f32 %0, %1;" : "=r"(r) : "f"(x));
    return r;
}

__device__ __forceinline__ void mma_tf32(float& c0, float& c1, float& c2, float& c3,
                                         unsigned a0, unsigned a1, unsigned a2, unsigned a3,
                                         unsigned b0, unsigned b1) {
    asm volatile(
        "mma.sync.aligned.m16n8k8.row.col.f32.tf32.tf32.f32 "
        "{%0,%1,%2,%3}, {%4,%5,%6,%7}, {%8,%9}, {%0,%1,%2,%3};\n"
        : "+f"(c0), "+f"(c1), "+f"(c2), "+f"(c3)
        : "r"(a0), "r"(a1), "r"(a2), "r"(a3), "r"(b0), "r"(b1));
}

__device__ __forceinline__ void load_a(unsigned a[8][4], const float* __restrict__ X,
                                       int xp, int lane) {
    int row = lane >> 2, kc = lane & 3;
    const float* p0 = X + row * xp + kc;
    const float* p1 = X + (row + 8) * xp + kc;
    #pragma unroll
    for (int kb = 0; kb < 8; kb++) {
        a[kb][0] = f2tf(p0[kb * 8]);
        a[kb][1] = f2tf(p1[kb * 8]);
        a[kb][2] = f2tf(p0[kb * 8 + 4]);
        a[kb][3] = f2tf(p1[kb * 8 + 4]);
    }
}

// EPI: 0 plain, 1 relu, 2 add residual R ; ROWS8: only rows 0..7 stored
template<int EPI, bool ROWS8>
__device__ __forceinline__ void gemm_tile(const unsigned a[8][4],
                                          const float* __restrict__ W,
                                          const float* __restrict__ bias,
                                          int jbase,
                                          float* __restrict__ C, int cp,
                                          const float* __restrict__ R, int rp,
                                          int lane) {
    int g = lane >> 2, tg = lane & 3;
    int col0 = jbase + 2 * tg;
    float2 bb = *(const float2*)(bias + col0);
    float c0 = bb.x, c1 = bb.y, c2 = bb.x, c3 = bb.y;
    const float* wr = W + (jbase + g) * PITCH;
    #pragma unroll
    for (int kb = 0; kb < 8; kb++) {
        unsigned b0 = __float_as_uint(wr[kb * 8 + tg]);
        unsigned b1 = __float_as_uint(wr[kb * 8 + tg + 4]);
        mma_tf32(c0, c1, c2, c3, a[kb][0], a[kb][1], a[kb][2], a[kb][3], b0, b1);
    }
    if (EPI == 2) {
        float2 r0 = *(const float2*)(R + g * rp + col0);
        float2 r1 = *(const float2*)(R + (g + 8) * rp + col0);
        c0 += r0.x; c1 += r0.y; c2 += r1.x; c3 += r1.y;
    }
    if (EPI == 1) {
        c0 = fmaxf(c0, 0.f); c1 = fmaxf(c1, 0.f);
        c2 = fmaxf(c2, 0.f); c3 = fmaxf(c3, 0.f);
    }
    *(float2*)(C + g * cp + col0) = make_float2(c0, c1);
    if (!ROWS8) *(float2*)(C + (g + 8) * cp + col0) = make_float2(c2, c3);
}

// ---------------- main per-edge transformer kernel ----------------

#define SUBBAR() asm volatile("bar.sync %0, 128;" :: "r"(sub + 1) : "memory")

__global__ void __launch_bounds__(512, 1)
edge_kernel(const int* __restrict__ ei, int dir,
            const float* __restrict__ bpw, const float* __restrict__ bpb,
            const float* __restrict__ ipw, const float* __restrict__ ipb,
            const float* __restrict__ opw, const float* __restrict__ opb,
            const float* __restrict__ ln1g, const float* __restrict__ ln1b,
            const float* __restrict__ ln2g, const float* __restrict__ ln2b,
            const float* __restrict__ w1,  const float* __restrict__ fb1,
            const float* __restrict__ w2,  const float* __restrict__ fb2) {
    extern __shared__ float sm[];
    float* s_ipw = sm;                          // 192*68
    float* s_opw = s_ipw + 192 * PITCH;
    float* s_w1  = s_opw + 64 * PITCH;
    float* s_w2  = s_w1  + 64 * PITCH;
    float* s_bw  = s_w2  + 64 * PITCH;
    float* s_b   = s_bw  + 64 * PITCH;          // 704 floats biases/ln
    float* s_act = s_b + 704;

    const float* hin  = dir ? g_hB : g_hA;
    float*       hout = dir ? g_hA : g_hB;

    const int tid = threadIdx.x;

    // ---- stage weights once, pre-rounded to tf32 ----
    for (int i = tid; i < 192 * 64; i += 512)
        s_ipw[(i >> 6) * PITCH + (i & 63)] = __uint_as_float(f2tf(ipw[i]));
    for (int i = tid; i < 64 * 64; i += 512) {
        int r = (i >> 6) * PITCH + (i & 63);
        s_opw[r] = __uint_as_float(f2tf(opw[i]));
        s_w1[r]  = __uint_as_float(f2tf(w1[i]));
        s_w2[r]  = __uint_as_float(f2tf(w2[i]));
        s_bw[r]  = __uint_as_float(f2tf(bpw[i]));
    }
    for (int i = tid; i < 192; i += 512) s_b[i] = ipb[i];
    if (tid < 64) {
        s_b[192 + tid] = opb[tid];  s_b[256 + tid] = fb1[tid];
        s_b[320 + tid] = fb2[tid];  s_b[384 + tid] = ln1g[tid];
        s_b[448 + tid] = ln1b[tid]; s_b[512 + tid] = ln2g[tid];
        s_b[576 + tid] = ln2b[tid]; s_b[640 + tid] = bpb[tid];
    }
    __syncthreads();

    const int sub  = tid >> 7;     // 0..3 edge slot
    const int st   = tid & 127;
    const int warp = st >> 5;
    const int lane = st & 31;
    const int g    = lane >> 2, tg = lane & 3;
    float* xs  = s_act + sub * 5888;       // 8*68
    float* xc  = xs + 8 * PITCH;           // 16*68
    float* qv  = xc + 16 * PITCH;          // 16*196 (q 0..63 | k 64..127 | vT 128..191)
    float* ao  = qv + 16 * QPITCH;         // 16*68  (P scratch / attn out / ff hidden)

    const int is64 = (g_any == 0);
    const int r0 = st >> 4, d0 = (st & 15) << 2;
    const int stride4 = gridDim.x * 4;

    // ---- prologue prefetch ----
    bool pv; int ptgt = 0; float pic = 0.f;
    float4 pvi = make_float4(0,0,0,0), pvj = pvi;
    {
        int e = blockIdx.x * 4 + sub;
        pv = e < EE;
        if (pv) {
            int src = is64 ? ei[2 * e]        : ei[e];
            ptgt    = is64 ? ei[2 * (EE + e)] : ei[EE + e];
            pic = g_inv[ptgt];
            pvi = *(const float4*)(hin + (size_t)ptgt * 512 + r0 * 64 + d0);
            pvj = *(const float4*)(hin + (size_t)src  * 512 + r0 * 64 + d0);
        }
    }

    for (int base = blockIdx.x * 4; base < EE; base += stride4) {
        const bool valid = pv;
        const int  tgt = ptgt;
        const float ic = pic;

        // ---- P0: commit prefetched gather to smem ----
        if (valid) {
            *(float4*)(xc + r0 * PITCH + d0) = pvi;
            *(float4*)(xs + r0 * PITCH + d0) = pvj;
        }
        SUBBAR();

        // ---- prefetch next iteration ----
        {
            int en = base + stride4 + sub;
            pv = en < EE;
            if (pv) {
                int src = is64 ? ei[2 * en]        : ei[en];
                ptgt    = is64 ? ei[2 * (EE + en)] : ei[EE + en];
                pic = g_inv[ptgt];
                pvi = *(const float4*)(hin + (size_t)ptgt * 512 + r0 * 64 + d0);
                pvj = *(const float4*)(hin + (size_t)src  * 512 + r0 * 64 + d0);
            }
        }

        // ---- P1: bproj -> xc rows 8..15 ----
        if (valid) {
            unsigned a[8][4];
            load_a(a, xs, PITCH, lane);
            gemm_tile<0, true>(a, s_bw, s_b + 640, warp * 16,     xc + 8 * PITCH, PITCH, 0, 0, lane);
            gemm_tile<0, true>(a, s_bw, s_b + 640, warp * 16 + 8, xc + 8 * PITCH, PITCH, 0, 0, lane);
        }
        SUBBAR();

        // ---- P2: qkv ; V stored transposed per head into vT region ----
        if (valid) {
            unsigned a[8][4];
            load_a(a, xc, PITCH, lane);
            #pragma unroll
            for (int nt = 0; nt < 6; nt++) {
                int jb = warp * 48 + nt * 8;
                float2 bb = *(const float2*)(s_b + jb + 2 * tg);
                float c0 = bb.x, c1 = bb.y, c2 = bb.x, c3 = bb.y;
                const float* wr = s_ipw + (jb + g) * PITCH;
                #pragma unroll
                for (int kb = 0; kb < 8; kb++) {
                    unsigned b0 = __float_as_uint(wr[kb * 8 + tg]);
                    unsigned b1 = __float_as_uint(wr[kb * 8 + tg + 4]);
                    mma_tf32(c0, c1, c2, c3, a[kb][0], a[kb][1], a[kb][2], a[kb][3], b0, b1);
                }
                if (jb < 128) {
                    *(float2*)(qv + g * QPITCH + jb + 2 * tg)       = make_float2(c0, c1);
                    *(float2*)(qv + (g + 8) * QPITCH + jb + 2 * tg) = make_float2(c2, c3);
                } else {
                    // transposed V store: vT[d][key] at qv[d&15][128 + 16*(d>>4) + key]
                    int dL = jb - 128 + 2 * tg;
                    float* vt = qv + 128 + 16 * (dL >> 4);
                    int dd = dL & 15;
                    vt[dd * QPITCH + g]           = c0;
                    vt[(dd + 1) * QPITCH + g]     = c1;
                    vt[dd * QPITCH + g + 8]       = c2;
                    vt[(dd + 1) * QPITCH + g + 8] = c3;
                }
            }
        }
        SUBBAR();

        // ---- P3: attention via MMA (warp = head) ----
        if (valid) {
            const float* qb  = qv + warp * 16;
            const float* kbp = qv + 64 + warp * 16;
            // A = Q fragments (16x16, 2 k-chunks)
            unsigned aq[2][4];
            #pragma unroll
            for (int kc = 0; kc < 2; kc++) {
                const float* p0 = qb + g * QPITCH + kc * 8 + tg;
                const float* p1 = qb + (g + 8) * QPITCH + kc * 8 + tg;
                aq[kc][0] = f2tf(p0[0]); aq[kc][1] = f2tf(p1[0]);
                aq[kc][2] = f2tf(p0[4]); aq[kc][3] = f2tf(p1[4]);
            }
            // scores: two n8 tiles (keys 0..7, 8..15)
            float s00, s01, s02, s03, s10, s11, s12, s13;
            {
                float c0 = 0, c1 = 0, c2 = 0, c3 = 0;
                #pragma unroll
                for (int kc = 0; kc < 2; kc++) {
                    const float* kr = kbp + g * QPITCH + kc * 8;
                    mma_tf32(c0, c1, c2, c3, aq[kc][0], aq[kc][1], aq[kc][2], aq[kc][3],
                             f2tf(kr[tg]), f2tf(kr[tg + 4]));
                }
                s00 = c0; s01 = c1; s02 = c2; s03 = c3;
            }
            {
                float c0 = 0, c1 = 0, c2 = 0, c3 = 0;
                #pragma unroll
                for (int kc = 0; kc < 2; kc++) {
                    const float* kr = kbp + (8 + g) * QPITCH + kc * 8;
                    mma_tf32(c0, c1, c2, c3, aq[kc][0], aq[kc][1], aq[kc][2], aq[kc][3],
                             f2tf(kr[tg]), f2tf(kr[tg + 4]));
                }
                s10 = c0; s11 = c1; s12 = c2; s13 = c3;
            }
            // softmax: row g owns (s00,s01,s10,s11); row g+8 owns (s02,s03,s12,s13)
            s00 *= 0.25f; s01 *= 0.25f; s02 *= 0.25f; s03 *= 0.25f;
            s10 *= 0.25f; s11 *= 0.25f; s12 *= 0.25f; s13 *= 0.25f;
            float m0 = fmaxf(fmaxf(s00, s01), fmaxf(s10, s11));
            float m1 = fmaxf(fmaxf(s02, s03), fmaxf(s12, s13));
            m0 = fmaxf(m0, __shfl_xor_sync(0xffffffffu, m0, 1));
            m0 = fmaxf(m0, __shfl_xor_sync(0xffffffffu, m0, 2));
            m1 = fmaxf(m1, __shfl_xor_sync(0xffffffffu, m1, 1));
            m1 = fmaxf(m1, __shfl_xor_sync(0xffffffffu, m1, 2));
            float e00 = __expf(s00 - m0), e01 = __expf(s01 - m0);
            float e10 = __expf(s10 - m0), e11 = __expf(s11 - m0);
            float e02 = __expf(s02 - m1), e03 = __expf(s03 - m1);
            float e12 = __expf(s12 - m1), e13 = __expf(s13 - m1);
            float t0 = (e00 + e01) + (e10 + e11);
            float t1 = (e02 + e03) + (e12 + e13);
            t0 += __shfl_xor_sync(0xffffffffu, t0, 1);
            t0 += __shfl_xor_sync(0xffffffffu, t0, 2);
            t1 += __shfl_xor_sync(0xffffffffu, t1, 1);
            t1 += __shfl_xor_sync(0xffffffffu, t1, 2);
            float r0s = 1.f / t0, r1s = 1.f / t1;
            // store normalized P into warp's private slice of ao
            float* pb = ao + warp * 16;
            *(float2*)(pb + g * PITCH + 2 * tg)           = make_float2(e00 * r0s, e01 * r0s);
            *(float2*)(pb + g * PITCH + 8 + 2 * tg)       = make_float2(e10 * r0s, e11 * r0s);
            *(float2*)(pb + (g + 8) * PITCH + 2 * tg)     = make_float2(e02 * r1s, e03 * r1s);
            *(float2*)(pb + (g + 8) * PITCH + 8 + 2 * tg) = make_float2(e12 * r1s, e13 * r1s);
            __syncwarp();
            // reload P as A fragments
            unsigned ap[2][4];
            #pragma unroll
            for (int kc = 0; kc < 2; kc++) {
                const float* p0 = pb + g * PITCH + kc * 8 + tg;
                const float* p1 = pb + (g + 8) * PITCH + kc * 8 + tg;
                ap[kc][0] = f2tf(p0[0]); ap[kc][1] = f2tf(p1[0]);
                ap[kc][2] = f2tf(p0[4]); ap[kc][3] = f2tf(p1[4]);
            }
            __syncwarp();   // all lanes done reading P before stores overwrite it
            // AV: B = vT (per-head [dim][key]) -> output ao[q][warp*16 + d]
            const float* vtb = qv + 128 + 16 * warp;
            #pragma unroll
            for (int jb2 = 0; jb2 < 2; jb2++) {
                float c0 = 0, c1 = 0, c2 = 0, c3 = 0;
                #pragma unroll
                for (int kc = 0; kc < 2; kc++) {
                    const float* vr = vtb + (jb2 * 8 + g) * QPITCH + kc * 8;
                    mma_tf32(c0, c1, c2, c3, ap[kc][0], ap[kc][1], ap[kc][2], ap[kc][3],
                             f2tf(vr[tg]), f2tf(vr[tg + 4]));
                }
                *(float2*)(ao + g * PITCH + warp * 16 + jb2 * 8 + 2 * tg)       = make_float2(c0, c1);
                *(float2*)(ao + (g + 8) * PITCH + warp * 16 + jb2 * 8 + 2 * tg) = make_float2(c2, c3);
            }
        }
        SUBBAR();

        // ---- P4: out_proj + residual -> qv ----
        if (valid) {
            unsigned a[8][4];
            load_a(a, ao, PITCH, lane);
            gemm_tile<2, false>(a, s_opw, s_b + 192, warp * 16,     qv, QPITCH, xc, PITCH, lane);
            gemm_tile<2, false>(a, s_opw, s_b + 192, warp * 16 + 8, qv, QPITCH, xc, PITCH, lane);
        }
        SUBBAR();

        // ---- LN1 (8 threads/row) -> xc ----
        if (valid) {
            int row = st >> 3, part = st & 7, c0i = part * 8;
            const float4* p = (const float4*)(qv + row * QPITCH + c0i);
            float4 u0 = p[0], u1 = p[1];
            float s = (u0.x + u0.y) + (u0.z + u0.w) + (u1.x + u1.y) + (u1.z + u1.w);
            s += __shfl_xor_sync(0xffffffffu, s, 1);
            s += __shfl_xor_sync(0xffffffffu, s, 2);
            s += __shfl_xor_sync(0xffffffffu, s, 4);
            float mu = s * 0.015625f;
            float t0 = u0.x - mu, t1 = u0.y - mu, t2 = u0.z - mu, t3 = u0.w - mu;
            float t4 = u1.x - mu, t5 = u1.y - mu, t6 = u1.z - mu, t7 = u1.w - mu;
            float v = t0*t0 + t1*t1 + t2*t2 + t3*t3 + t4*t4 + t5*t5 + t6*t6 + t7*t7;
            v += __shfl_xor_sync(0xffffffffu, v, 1);
            v += __shfl_xor_sync(0xffffffffu, v, 2);
            v += __shfl_xor_sync(0xffffffffu, v, 4);
            float rstd = rsqrtf(v * 0.015625f + 1e-5f);
            const float4 g0 = *(const float4*)(s_b + 384 + c0i);
            const float4 g1 = *(const float4*)(s_b + 384 + c0i + 4);
            const float4 bb0 = *(const float4*)(s_b + 448 + c0i);
            const float4 bb1 = *(const float4*)(s_b + 448 + c0i + 4);
            float4 o0, o1;
            o0.x = t0 * rstd * g0.x + bb0.x; o0.y = t1 * rstd * g0.y + bb0.y;
            o0.z = t2 * rstd * g0.z + bb0.z; o0.w = t3 * rstd * g0.w + bb0.w;
            o1.x = t4 * rstd * g1.x + bb1.x; o1.y = t5 * rstd * g1.y + bb1.y;
            o1.z = t6 * rstd * g1.z + bb1.z; o1.w = t7 * rstd * g1.w + bb1.w;
            *(float4*)(xc + row * PITCH + c0i) = o0;
            *(float4*)(xc + row * PITCH + c0i + 4) = o1;
        }
        SUBBAR();

        // ---- P6: FF1 + relu -> ao ----
        if (valid) {
            unsigned a[8][4];
            load_a(a, xc, PITCH, lane);
            gemm_tile<1, false>(a, s_w1, s_b + 256, warp * 16,     ao, PITCH, 0, 0, lane);
            gemm_tile<1, false>(a, s_w1, s_b + 256, warp * 16 + 8, ao, PITCH, 0, 0, lane);
        }
        SUBBAR();

        // ---- P7: FF2 + residual -> qv ----
        if (valid) {
            unsigned a[8][4];
            load_a(a, ao, PITCH, lane);
            gemm_tile<2, false>(a, s_w2, s_b + 320, warp * 16,     qv, QPITCH, xc, PITCH, lane);
            gemm_tile<2, false>(a, s_w2, s_b + 320, warp * 16 + 8, qv, QPITCH, xc, PITCH, lane);
        }
        SUBBAR();

        // ---- LN2 (rows 0..7) fused with scaled atomic scatter ----
        if (valid) {
            int row = st >> 4, part = st & 15, c0i = part * 4;
            float4 u = *(const float4*)(qv + row * QPITCH + c0i);
            float s = (u.x + u.y) + (u.z + u.w);
            s += __shfl_xor_sync(0xffffffffu, s, 1);
            s += __shfl_xor_sync(0xffffffffu, s, 2);
            s += __shfl_xor_sync(0xffffffffu, s, 4);
            s += __shfl_xor_sync(0xffffffffu, s, 8);
            float mu = s * 0.015625f;
            float t0 = u.x - mu, t1 = u.y - mu, t2 = u.z - mu, t3 = u.w - mu;
            float v = t0*t0 + t1*t1 + t2*t2 + t3*t3;
            v += __shfl_xor_sync(0xffffffffu, v, 1);
            v += __shfl_xor_sync(0xffffffffu, v, 2);
            v += __shfl_xor_sync(0xffffffffu, v, 4);
            v += __shfl_xor_sync(0xffffffffu, v, 8);
            float rstd = rsqrtf(v * 0.015625f + 1e-5f);
            const float4 gg = *(const float4*)(s_b + 512 + c0i);
            const float4 bb = *(const float4*)(s_b + 576 + c0i);
            float* dst = hout + (size_t)tgt * 512 + row * 64 + c0i;
            atomicAdd(dst + 0, (t0 * rstd * gg.x + bb.x) * ic);
            atomicAdd(dst + 1, (t1 * rstd * gg.y + bb.y) * ic);
            atomicAdd(dst + 2, (t2 * rstd * gg.z + bb.z) * ic);
            atomicAdd(dst + 3, (t3 * rstd * gg.w + bb.w) * ic);
        }
        // no trailing barrier: next write to qv is P2 (two barriers away)
    }
}

// ---------------- output head ----------------
__global__ void out_kernel(const float* __restrict__ ow,
                           const float* __restrict__ ob,
                           float* __restrict__ out) {
    __shared__ float shs[8][64];
    int w = threadIdx.x >> 5, lane = threadIdx.x & 31;
    int n = blockIdx.x * 8 + w;
    if (n >= NN) return;
    const float* hr = g_hA + (size_t)n * 512;
    float lo = 0.f, hi = 0.f;
    #pragma unroll
    for (int c = 0; c < 8; c++) { lo += hr[c * 64 + lane]; hi += hr[c * 64 + 32 + lane]; }
    shs[w][lane] = lo; shs[w][lane + 32] = hi;
    __syncwarp();
    float z = -1e30f;
    if (lane < 16) {
        float acc = 8.f * ob[lane];
        const float* wr = ow + lane * 64;
        #pragma unroll
        for (int d = 0; d < 64; d++) acc = fmaf(shs[w][d], wr[d], acc);
        z = acc;
    }
    float m = z;
    #pragma unroll
    for (int off = 8; off; off >>= 1) m = fmaxf(m, __shfl_xor_sync(0xffffffffu, m, off, 16));
    float p = __expf(z - m);
    float s = p;
    #pragma unroll
    for (int off = 8; off; off >>= 1) s += __shfl_xor_sync(0xffffffffu, s, off, 16);
    if (lane < 16) out[n * 16 + lane] = p / s;
}

// ---------------- launch ----------------
extern "C" void kernel_launch(void* const* d_in, const int* in_sizes, int n_in,
                              void* d_out, int out_size) {
    const float* x    = (const float*)d_in[0];
    const int*   ei   = (const int*)d_in[1];
    const float* numw = (const float*)d_in[2];
    const float* numb = (const float*)d_in[3];
    const float* bpw  = (const float*)d_in[4];
    const float* bpb  = (const float*)d_in[5];
    const float* ipw  = (const float*)d_in[6];
    const float* ipb  = (const float*)d_in[7];
    const float* opw  = (const float*)d_in[8];
    const float* opb  = (const float*)d_in[9];
    const float* g1   = (const float*)d_in[10];
    const float* b1   = (const float*)d_in[11];
    const float* g2   = (const float*)d_in[12];
    const float* b2   = (const float*)d_in[13];
    const float* w1   = (const float*)d_in[14];
    const float* fb1  = (const float*)d_in[15];
    const float* w2   = (const float*)d_in[16];
    const float* fb2  = (const float*)d_in[17];
    const float* ow   = (const float*)d_in[18];
    const float* ob   = (const float*)d_in[19];
    float* out = (float*)d_out;

    const int SMEM_BYTES = (192 * PITCH + 4 * 64 * PITCH + 704 + 4 * 5888) * 4;
    cudaFuncSetAttribute(edge_kernel, cudaFuncAttributeMaxDynamicSharedMemorySize, SMEM_BYTES);

    int dev = 0, sms = 148;
    cudaGetDevice(&dev);
    cudaDeviceGetAttribute(&sms, cudaDevAttrMultiProcessorCount, dev);

    setup0_kernel<<<(NN * 128 + 255) / 256, 256>>>();
    detect_kernel<<<256, 256>>>(ei);
    embed_kernel<<<(NN * 512 + 255) / 256, 256>>>(x, numw, numb);
    count_kernel<<<(EE + 255) / 256, 256>>>(ei);
    fin_cnt_kernel<<<(NN + 255) / 256, 256>>>();

    // layer 0: A -> B
    edge_kernel<<<sms, 512, SMEM_BYTES>>>(ei, 0,
        bpw, bpb, ipw, ipb, opw, opb, g1, b1, g2, b2, w1, fb1, w2, fb2);

    // layer 1: B -> A
    zeroA_kernel<<<(NN * 128 + 255) / 256, 256>>>();
    edge_kernel<<<sms, 512, SMEM_BYTES>>>(ei, 1,
        bpw + 64 * 64, bpb + 64, ipw + 192 * 64, ipb + 192, opw + 64 * 64, opb + 64,
        g1 + 64, b1 + 64, g2 + 64, b2 + 64,
        w1 + 64 * 64, fb1 + 64, w2 + 64 * 64, fb2 + 64);

    out_kernel<<<(NN + 7) / 8, 256>>>(ow, ob, out);
}